// round 9
// baseline (speedup 1.0000x reference)
#include <cuda_runtime.h>
#include <cuda_fp16.h>
#include <cstdint>

// UnionLayer via Taylor expansion -> fp16 tensor-core GEMM (mma.sync, generic PTX).
//   -log(1-t) = sum_{n=1..7} t^n / n,  t = u*w in [0, 0.5)
//   S[b,nh]   = sum_d sum_n u^n * (w^n / n)  == GEMM, K = 7*512
//   con: u = 1-x, y = 1/(1+S);  dis: u = x, y = 1 - 1/(1+S)
// R9: 512-thread CTA, split-K x4, REGISTER-LEAN (fits 128 regs, no spills):
//   d processed in 16-wide halves -> chain/staging fragments are [4][2] not [4][4].
//   warp w: m-slice (w&3)*32, d-quarter (w>>2)*128 (4 chunks x 32 d, 2 halves each)
//   -> 4 warps/SMSP. Software prefetch of next half kept. 48KB smem reduction.
// Grid (8, 8, 2) = 128 CTAs, 1 per SM.

#define DDIM    512
#define NOUT    512
#define NCOLS   256
#define NTERMS  7
#define MTILE   128
#define NTILE   32
#define THREADS 512
#define RED_BYTES (3 * 4 * 32 * 32 * 4)   // 49152

__device__ __forceinline__ void mma16816(float* c, uint32_t a0, uint32_t a1,
                                         uint32_t a2, uint32_t a3,
                                         uint32_t b0, uint32_t b1) {
    asm volatile(
        "mma.sync.aligned.m16n8k16.row.col.f32.f16.f16.f32 "
        "{%0,%1,%2,%3}, {%4,%5,%6,%7}, {%8,%9}, {%0,%1,%2,%3};"
        : "+f"(c[0]), "+f"(c[1]), "+f"(c[2]), "+f"(c[3])
        : "r"(a0), "r"(a1), "r"(a2), "r"(a3), "r"(b0), "r"(b1));
}

__device__ __forceinline__ uint32_t h2u(__half2 h) {
    return *reinterpret_cast<uint32_t*>(&h);
}

__global__ __launch_bounds__(THREADS) void union_mma_kernel(
    const float* __restrict__ x,
    const float* __restrict__ Wcon,
    const float* __restrict__ Wdis,
    float* __restrict__ out)
{
    extern __shared__ float red[];   // [3][4][32*32] partial tiles from d-quarters 1..3

    const int tid  = threadIdx.x;
    const int wid  = tid >> 5;
    const int lane = tid & 31;
    const int g    = lane >> 2;        // 0..7
    const int t4   = lane & 3;         // 0..3
    const int msl  = wid & 3;          // m-slice (32 rows each)
    const int dq   = wid >> 2;         // d-quarter 0..3
    const int bn0  = blockIdx.x * NTILE;
    const int bm0  = blockIdx.y * MTILE;
    const int z    = blockIdx.z;       // 0 = con, 1 = dis
    const float* __restrict__ W = z ? Wdis : Wcon;

    const float* __restrict__ pA = &x[(bm0 + msl * 32 + g) * DDIM + dq * 128 + 2 * t4];
    const float* __restrict__ pB = &W[(bn0 + g) * DDIM + dq * 128 + 2 * t4];

    float acc[2][4][4];
#pragma unroll
    for (int mt = 0; mt < 2; mt++)
#pragma unroll
        for (int nt = 0; nt < 4; nt++)
#pragma unroll
            for (int c = 0; c < 4; c++) acc[mt][nt][c] = 0.0f;

    // staged raw loads for one 16-d half: [row][pair]
    float2 sA[4][2], sB[4][2];
#pragma unroll
    for (int r = 0; r < 4; r++)
#pragma unroll
        for (int p = 0; p < 2; p++) {
            sA[r][p] = *reinterpret_cast<const float2*>(pA + r * 8 * DDIM + p * 8);
            sB[r][p] = *reinterpret_cast<const float2*>(pB + r * 8 * DDIM + p * 8);
        }

    const float kf[NTERMS] = {0.f, 0.5f, 2.f/3.f, 0.75f, 0.8f, 5.f/6.f, 6.f/7.f};

#pragma unroll
    for (int ck = 0; ck < 4; ck++) {
#pragma unroll
        for (int hf = 0; hf < 2; hf++) {
            // ---- build half2 bases from staged raw ----
            __half2 baseA[4][2], baseB[4][2], curA[4][2], curB[4][2];
#pragma unroll
            for (int r = 0; r < 4; r++)
#pragma unroll
                for (int p = 0; p < 2; p++) {
                    float ux = sA[r][p].x, uy = sA[r][p].y;
                    if (z == 0) { ux = 1.0f - ux; uy = 1.0f - uy; }
                    baseA[r][p] = __floats2half2_rn(ux, uy);
                    baseB[r][p] = __floats2half2_rn(sB[r][p].x, sB[r][p].y);
                    curA[r][p]  = baseA[r][p];
                    curB[r][p]  = baseB[r][p];
                }

            // ---- prefetch next 16-d half (hidden under term loop) ----
            {
                int nidx = ck * 2 + hf + 1;         // next half index 0..7
                if (nidx < 8) {
                    int off = nidx * 16;
#pragma unroll
                    for (int r = 0; r < 4; r++)
#pragma unroll
                        for (int p = 0; p < 2; p++) {
                            sA[r][p] = *reinterpret_cast<const float2*>(
                                pA + r * 8 * DDIM + off + p * 8);
                            sB[r][p] = *reinterpret_cast<const float2*>(
                                pB + r * 8 * DDIM + off + p * 8);
                        }
                }
            }

            // ---- 7 Taylor terms, one k16 MMA block each ----
#pragma unroll
            for (int n = 0; n < NTERMS; n++) {
                if (n) {
                    const __half2 kfh = __float2half2_rn(kf[n]);
#pragma unroll
                    for (int r = 0; r < 4; r++)
#pragma unroll
                        for (int p = 0; p < 2; p++) {
                            curA[r][p] = __hmul2(curA[r][p], baseA[r][p]);
                            curB[r][p] = __hmul2(__hmul2(curB[r][p], baseB[r][p]), kfh);
                        }
                }
#pragma unroll
                for (int mt = 0; mt < 2; mt++) {
                    uint32_t a0 = h2u(curA[mt * 2 + 0][0]);
                    uint32_t a1 = h2u(curA[mt * 2 + 1][0]);
                    uint32_t a2 = h2u(curA[mt * 2 + 0][1]);
                    uint32_t a3 = h2u(curA[mt * 2 + 1][1]);
#pragma unroll
                    for (int nt = 0; nt < 4; nt++) {
                        mma16816(acc[mt][nt], a0, a1, a2, a3,
                                 h2u(curB[nt][0]), h2u(curB[nt][1]));
                    }
                }
            }
        }
    }

    // ---- merge d-quarters: q1..q3 store partials, q0 adds + epilogue ----
    if (dq != 0) {
        float* tile = &red[((dq - 1) * 4 + msl) * 1024];
#pragma unroll
        for (int mt = 0; mt < 2; mt++)
#pragma unroll
            for (int hh = 0; hh < 2; hh++) {
                int r = mt * 16 + hh * 8 + g;
#pragma unroll
                for (int nt = 0; nt < 4; nt++) {
                    *reinterpret_cast<float2*>(&tile[r * 32 + nt * 8 + 2 * t4]) =
                        make_float2(acc[mt][nt][hh * 2 + 0], acc[mt][nt][hh * 2 + 1]);
                }
            }
    }
    __syncthreads();

    if (dq == 0) {
#pragma unroll
        for (int mt = 0; mt < 2; mt++) {
#pragma unroll
            for (int hh = 0; hh < 2; hh++) {
                int r = mt * 16 + hh * 8 + g;
                int m = bm0 + msl * 32 + r;
#pragma unroll
                for (int nt = 0; nt < 4; nt++) {
                    float S0 = acc[mt][nt][hh * 2 + 0];
                    float S1 = acc[mt][nt][hh * 2 + 1];
#pragma unroll
                    for (int q = 0; q < 3; q++) {
                        float2 o = *reinterpret_cast<const float2*>(
                            &red[(q * 4 + msl) * 1024 + r * 32 + nt * 8 + 2 * t4]);
                        S0 += o.x;
                        S1 += o.y;
                    }
                    float y0 = 1.0f / (1.0f + S0);
                    float y1 = 1.0f / (1.0f + S1);
                    if (z) { y0 = 1.0f - y0; y1 = 1.0f - y1; }
                    int col = bn0 + nt * 8 + 2 * t4;
                    *reinterpret_cast<float2*>(&out[m * NOUT + z * NCOLS + col]) =
                        make_float2(y0, y1);
                }
            }
        }
    }
}

extern "C" void kernel_launch(void* const* d_in, const int* in_sizes, int n_in,
                              void* d_out, int out_size)
{
    const float* x    = (const float*)d_in[0];
    const float* Wcon = (const float*)d_in[1];
    const float* Wdis = (const float*)d_in[2];
    float* out = (float*)d_out;

    cudaFuncSetAttribute(union_mma_kernel,
                         cudaFuncAttributeMaxDynamicSharedMemorySize, RED_BYTES);

    dim3 grid(NCOLS / NTILE, 1024 / MTILE, 2);   // (8, 8, 2) = 128 CTAs
    union_mma_kernel<<<grid, THREADS, RED_BYTES>>>(x, Wcon, Wdis, out);
}

// round 10
// speedup vs baseline: 1.0975x; 1.0975x over previous
#include <cuda_runtime.h>
#include <cuda_fp16.h>
#include <cstdint>

// UnionLayer via Taylor expansion -> fp16 tensor-core GEMM (mma.sync, generic PTX).
//   -log(1-t) = sum_{n=1..7} t^n / n,  t = u*w in [0, 0.5)
//   S[b,nh]   = sum_d sum_n u^n * (w^n / n)  == GEMM, K = 7*512
//   con: u = 1-x, y = 1/(1+S);  dis: u = x, y = 1 - 1/(1+S)
// R10 = R8 base (256 thr, 8 warps: 4 m-slices x 2 d-halves) with term-level
// SOFTWARE PIPELINING: power chains for term n+1 are computed into an
// alternate register buffer BEFORE term n's MMAs issue -> no chain->MMA RAW
// at issue, fma and tensor pipes overlap within each warp.
// Also: B chain restructured (bb = base*kf independent, then curB*=bb),
// per-warp chunk-order stagger to decorrelate LDG bursts.
// d processed in 16-wide units (16 units/warp). Grid (8, 8, 2) = 128 CTAs.

#define DDIM    512
#define NOUT    512
#define NCOLS   256
#define NTERMS  7
#define MTILE   128
#define NTILE   32
#define THREADS 256

__device__ __forceinline__ void mma16816(float* c, uint32_t a0, uint32_t a1,
                                         uint32_t a2, uint32_t a3,
                                         uint32_t b0, uint32_t b1) {
    asm volatile(
        "mma.sync.aligned.m16n8k16.row.col.f32.f16.f16.f32 "
        "{%0,%1,%2,%3}, {%4,%5,%6,%7}, {%8,%9}, {%0,%1,%2,%3};"
        : "+f"(c[0]), "+f"(c[1]), "+f"(c[2]), "+f"(c[3])
        : "r"(a0), "r"(a1), "r"(a2), "r"(a3), "r"(b0), "r"(b1));
}

__device__ __forceinline__ uint32_t h2u(__half2 h) {
    return *reinterpret_cast<uint32_t*>(&h);
}

__global__ __launch_bounds__(THREADS) void union_mma_kernel(
    const float* __restrict__ x,
    const float* __restrict__ Wcon,
    const float* __restrict__ Wdis,
    float* __restrict__ out)
{
    __shared__ float red[4][32][32];   // d-half-1 partials (16 KB)

    const int tid  = threadIdx.x;
    const int wid  = tid >> 5;
    const int lane = tid & 31;
    const int g    = lane >> 2;        // 0..7
    const int t4   = lane & 3;         // 0..3
    const int msl  = wid & 3;          // m-slice (32 rows)
    const int dh   = wid >> 2;         // d-half 0/1
    const int bn0  = blockIdx.x * NTILE;
    const int bm0  = blockIdx.y * MTILE;
    const int z    = blockIdx.z;       // 0 = con, 1 = dis
    const float* __restrict__ W = z ? Wdis : Wcon;

    const float* __restrict__ pA = &x[(bm0 + msl * 32 + g) * DDIM + dh * 256 + 2 * t4];
    const float* __restrict__ pB = &W[(bn0 + g) * DDIM + dh * 256 + 2 * t4];

    float acc[2][4][4];
#pragma unroll
    for (int mt = 0; mt < 2; mt++)
#pragma unroll
        for (int nt = 0; nt < 4; nt++)
#pragma unroll
            for (int c = 0; c < 4; c++) acc[mt][nt][c] = 0.0f;

    const float kf[NTERMS] = {0.f, 0.5f, 2.f/3.f, 0.75f, 0.8f, 5.f/6.f, 6.f/7.f};
    const int stag = msl * 4;          // per-warp unit-order stagger

    // staged raw for one 16-d unit: [row][pair]  (pair p -> d offset p*8 + {0,1})
    float2 sA[4][2], sB[4][2];
    {
        int off = ((0 + stag) & 15) * 16;
#pragma unroll
        for (int r = 0; r < 4; r++)
#pragma unroll
            for (int p = 0; p < 2; p++) {
                sA[r][p] = *reinterpret_cast<const float2*>(pA + r * 8 * DDIM + off + p * 8);
                sB[r][p] = *reinterpret_cast<const float2*>(pB + r * 8 * DDIM + off + p * 8);
            }
    }

#pragma unroll 1
    for (int u = 0; u < 16; u++) {
        // ---- build bases + term-1 fragments (buffer 0) ----
        __half2 baseA[4][2], baseB[4][2], curA[2][4][2], curB[2][4][2];
#pragma unroll
        for (int r = 0; r < 4; r++)
#pragma unroll
            for (int p = 0; p < 2; p++) {
                float ux = sA[r][p].x, uy = sA[r][p].y;
                if (z == 0) { ux = 1.0f - ux; uy = 1.0f - uy; }
                baseA[r][p]   = __floats2half2_rn(ux, uy);
                baseB[r][p]   = __floats2half2_rn(sB[r][p].x, sB[r][p].y);
                curA[0][r][p] = baseA[r][p];
                curB[0][r][p] = baseB[r][p];
            }

        // ---- prefetch next unit's raw (consumed next iteration) ----
        if (u + 1 < 16) {
            int off = ((u + 1 + stag) & 15) * 16;
#pragma unroll
            for (int r = 0; r < 4; r++)
#pragma unroll
                for (int p = 0; p < 2; p++) {
                    sA[r][p] = *reinterpret_cast<const float2*>(pA + r * 8 * DDIM + off + p * 8);
                    sB[r][p] = *reinterpret_cast<const float2*>(pB + r * 8 * DDIM + off + p * 8);
                }
        }

        // ---- 7 terms, software-pipelined: chain(n+1) issued BEFORE mma(n) ----
#pragma unroll
        for (int n = 0; n < NTERMS; n++) {
            const int cb = n & 1, nb = (n + 1) & 1;
            if (n + 1 < NTERMS) {
                const __half2 kfh = __float2half2_rn(kf[n + 1]);
#pragma unroll
                for (int r = 0; r < 4; r++)
#pragma unroll
                    for (int p = 0; p < 2; p++) {
                        curA[nb][r][p] = __hmul2(curA[cb][r][p], baseA[r][p]);
                        __half2 bb    = __hmul2(baseB[r][p], kfh);     // independent
                        curB[nb][r][p] = __hmul2(curB[cb][r][p], bb);  // 1 dependent link
                    }
            }
#pragma unroll
            for (int mt = 0; mt < 2; mt++) {
                uint32_t a0 = h2u(curA[cb][mt * 2 + 0][0]);
                uint32_t a1 = h2u(curA[cb][mt * 2 + 1][0]);
                uint32_t a2 = h2u(curA[cb][mt * 2 + 0][1]);
                uint32_t a3 = h2u(curA[cb][mt * 2 + 1][1]);
#pragma unroll
                for (int nt = 0; nt < 4; nt++) {
                    mma16816(acc[mt][nt], a0, a1, a2, a3,
                             h2u(curB[cb][nt][0]), h2u(curB[cb][nt][1]));
                }
            }
        }
    }

    // ---- merge d-halves: half 1 stores, half 0 adds + epilogue ----
    if (dh == 1) {
#pragma unroll
        for (int mt = 0; mt < 2; mt++)
#pragma unroll
            for (int hh = 0; hh < 2; hh++) {
                int r = mt * 16 + hh * 8 + g;
#pragma unroll
                for (int nt = 0; nt < 4; nt++) {
                    *reinterpret_cast<float2*>(&red[msl][r][nt * 8 + 2 * t4]) =
                        make_float2(acc[mt][nt][hh * 2 + 0], acc[mt][nt][hh * 2 + 1]);
                }
            }
    }
    __syncthreads();

    if (dh == 0) {
#pragma unroll
        for (int mt = 0; mt < 2; mt++) {
#pragma unroll
            for (int hh = 0; hh < 2; hh++) {
                int r = mt * 16 + hh * 8 + g;
                int m = bm0 + msl * 32 + r;
#pragma unroll
                for (int nt = 0; nt < 4; nt++) {
                    float2 o = *reinterpret_cast<const float2*>(&red[msl][r][nt * 8 + 2 * t4]);
                    float S0 = acc[mt][nt][hh * 2 + 0] + o.x;
                    float S1 = acc[mt][nt][hh * 2 + 1] + o.y;
                    float y0 = 1.0f / (1.0f + S0);
                    float y1 = 1.0f / (1.0f + S1);
                    if (z) { y0 = 1.0f - y0; y1 = 1.0f - y1; }
                    int col = bn0 + nt * 8 + 2 * t4;
                    *reinterpret_cast<float2*>(&out[m * NOUT + z * NCOLS + col]) =
                        make_float2(y0, y1);
                }
            }
        }
    }
}

extern "C" void kernel_launch(void* const* d_in, const int* in_sizes, int n_in,
                              void* d_out, int out_size)
{
    const float* x    = (const float*)d_in[0];
    const float* Wcon = (const float*)d_in[1];
    const float* Wdis = (const float*)d_in[2];
    float* out = (float*)d_out;

    dim3 grid(NCOLS / NTILE, 1024 / MTILE, 2);   // (8, 8, 2) = 128 CTAs
    union_mma_kernel<<<grid, THREADS>>>(x, Wcon, Wdis, out);
}